// round 1
// baseline (speedup 1.0000x reference)
#include <cuda_runtime.h>
#include <math.h>

// ---------------- problem constants ----------------
#define D    768
#define DH   3072
#define BB   8
#define TT   8
#define HWQ  196            // H*W
#define NT   197            // tokens per frame (cls + 196)
#define BT   64             // B*T
#define NHD  12             // heads
#define HD   64             // head dim
#define ST   1569           // T*H*W + 1
#define MXT  (BT*NT)        // 12608 rows in frame-token space
#define MY   (BB*ST)        // 12552 rows in original token space
#define YSZ  (MY*D)         // 9,639,936
#define LMSZ (BT*NT*NT)     // 2,483,776

// ---------------- scratch (device globals: allocation-free) ----------------
__device__ float g_xt [MXT*D];
__device__ float g_qm [MXT*D];
__device__ float g_km [MXT*D];
__device__ float g_xn [MXT*D];        // reused: LN1 out, later LN2 out
__device__ float g_qkv[MXT*3*D];
__device__ float g_attn[(long)BT*NHD*NT*NT];
__device__ float g_o  [MXT*D];
__device__ float g_op [MXT*D];
__device__ float g_h  [MY*DH];

// ---------------- gather x -> xt (frame-token layout) ----------------
__global__ void gather_xt(const float* __restrict__ x, float* __restrict__ xt, int total) {
    int idx = blockIdx.x * blockDim.x + threadIdx.x;
    if (idx >= total) return;
    int d   = idx % D;
    int row = idx / D;
    int n   = row % NT;
    int bt  = row / NT;
    int b = bt / TT, t = bt % TT;
    int src = (n == 0) ? (b * ST) : (b * ST + 1 + (n - 1) * TT + t);
    xt[idx] = x[(long)src * D + d];
}

// ---------------- big NT SGEMM: C = epi(A*B^T + bias) ----------------
// A: MxK row-major, B: NxK row-major. ep: 0=bias, 1=bias+gelu, 2=bias+residual
__global__ __launch_bounds__(256) void sgemm_nt(
    const float* __restrict__ A, const float* __restrict__ B,
    const float* __restrict__ bias, const float* __restrict__ Res,
    float* __restrict__ C, int M, int Nn, int K, int ep)
{
    __shared__ __align__(16) float As[8][128];
    __shared__ __align__(16) float Bs[8][128];
    int tid = threadIdx.x;
    int m0 = blockIdx.y * 128, n0 = blockIdx.x * 128;
    int lrow = tid >> 1;            // 0..127
    int lcol = (tid & 1) * 4;       // 0 or 4
    int tx = tid & 15, ty = tid >> 4;
    float acc[8][8];
    #pragma unroll
    for (int i = 0; i < 8; i++)
        #pragma unroll
        for (int j = 0; j < 8; j++) acc[i][j] = 0.f;

    for (int k0 = 0; k0 < K; k0 += 8) {
        float4 av = make_float4(0.f,0.f,0.f,0.f), bv = make_float4(0.f,0.f,0.f,0.f);
        if (m0 + lrow < M)  av = *(const float4*)(A + (long)(m0 + lrow) * K + k0 + lcol);
        if (n0 + lrow < Nn) bv = *(const float4*)(B + (long)(n0 + lrow) * K + k0 + lcol);
        __syncthreads();
        As[lcol+0][lrow] = av.x; As[lcol+1][lrow] = av.y;
        As[lcol+2][lrow] = av.z; As[lcol+3][lrow] = av.w;
        Bs[lcol+0][lrow] = bv.x; Bs[lcol+1][lrow] = bv.y;
        Bs[lcol+2][lrow] = bv.z; Bs[lcol+3][lrow] = bv.w;
        __syncthreads();
        #pragma unroll
        for (int k = 0; k < 8; k++) {
            float4 a0 = *(const float4*)&As[k][ty*8];
            float4 a1 = *(const float4*)&As[k][ty*8+4];
            float4 b0 = *(const float4*)&Bs[k][tx*8];
            float4 b1 = *(const float4*)&Bs[k][tx*8+4];
            float a[8] = {a0.x,a0.y,a0.z,a0.w,a1.x,a1.y,a1.z,a1.w};
            float b[8] = {b0.x,b0.y,b0.z,b0.w,b1.x,b1.y,b1.z,b1.w};
            #pragma unroll
            for (int i = 0; i < 8; i++)
                #pragma unroll
                for (int j = 0; j < 8; j++) acc[i][j] = fmaf(a[i], b[j], acc[i][j]);
        }
    }
    #pragma unroll
    for (int i = 0; i < 8; i++) {
        int m = m0 + ty*8 + i;
        if (m >= M) continue;
        #pragma unroll
        for (int j = 0; j < 8; j++) {
            int n = n0 + tx*8 + j;
            if (n >= Nn) continue;
            float v = acc[i][j];
            if (bias) v += bias[n];
            if (ep == 1) v = 0.5f * v * (1.0f + erff(v * 0.7071067811865476f));
            else if (ep == 2) v += Res[(long)m * Nn + n];
            C[(long)m * Nn + n] = v;
        }
    }
}

// ---------------- batched-strided NT GEMM (64x64 tiles) ----------------
// batch z: outer = z/inner, in = z%inner. Used for lm logits and q*k^T scores.
__global__ __launch_bounds__(256) void bgemm_nt(
    const float* __restrict__ A, const float* __restrict__ B, float* __restrict__ C,
    int M, int Nn, int K, int lda, int ldb, int ldc,
    int inner, int sAi, int sBi, long long sAo, long long sBo, long long sC, float alpha)
{
    int z  = blockIdx.z;
    int zo = z / inner, zi = z % inner;
    const float* Ab = A + (long long)zo * sAo + (long long)zi * sAi;
    const float* Bb = B + (long long)zo * sBo + (long long)zi * sBi;
    float* Cb = C + (long long)z * sC;

    __shared__ __align__(16) float As[16][64];
    __shared__ __align__(16) float Bs[16][64];
    int tid = threadIdx.x;
    int m0 = blockIdx.y * 64, n0 = blockIdx.x * 64;
    int lr = tid >> 2;          // 0..63
    int lc = (tid & 3) * 4;     // 0,4,8,12
    int tx = tid & 15, ty = tid >> 4;
    float acc[4][4];
    #pragma unroll
    for (int i = 0; i < 4; i++)
        #pragma unroll
        for (int j = 0; j < 4; j++) acc[i][j] = 0.f;

    for (int k0 = 0; k0 < K; k0 += 16) {
        float4 av = make_float4(0.f,0.f,0.f,0.f), bv = make_float4(0.f,0.f,0.f,0.f);
        if (m0 + lr < M)  av = *(const float4*)(Ab + (long)(m0 + lr) * lda + k0 + lc);
        if (n0 + lr < Nn) bv = *(const float4*)(Bb + (long)(n0 + lr) * ldb + k0 + lc);
        __syncthreads();
        As[lc+0][lr] = av.x; As[lc+1][lr] = av.y; As[lc+2][lr] = av.z; As[lc+3][lr] = av.w;
        Bs[lc+0][lr] = bv.x; Bs[lc+1][lr] = bv.y; Bs[lc+2][lr] = bv.z; Bs[lc+3][lr] = bv.w;
        __syncthreads();
        #pragma unroll
        for (int k = 0; k < 16; k++) {
            float4 a4 = *(const float4*)&As[k][ty*4];
            float4 b4 = *(const float4*)&Bs[k][tx*4];
            float a[4] = {a4.x,a4.y,a4.z,a4.w};
            float b[4] = {b4.x,b4.y,b4.z,b4.w};
            #pragma unroll
            for (int i = 0; i < 4; i++)
                #pragma unroll
                for (int j = 0; j < 4; j++) acc[i][j] = fmaf(a[i], b[j], acc[i][j]);
        }
    }
    #pragma unroll
    for (int i = 0; i < 4; i++) {
        int m = m0 + ty*4 + i;
        if (m >= M) continue;
        #pragma unroll
        for (int j = 0; j < 4; j++) {
            int n = n0 + tx*4 + j;
            if (n < Nn) Cb[(long)m * ldc + n] = alpha * acc[i][j];
        }
    }
}

// ---------------- sigmoid over lm logits (with forced [0,0]=100) ----------------
__global__ void sigmoid_lm(float* __restrict__ lm, int total) {
    int idx = blockIdx.x * blockDim.x + threadIdx.x;
    if (idx >= total) return;
    int r = idx % (NT * NT);
    float v = (r == 0) ? 100.0f : lm[idx];
    lm[idx] = 1.0f / (1.0f + expf(-v));
}

// ---------------- LayerNorm over rows of 768 ----------------
__global__ void ln_kernel(const float* __restrict__ X, const float* __restrict__ g,
                          const float* __restrict__ be, float* __restrict__ Y) {
    int row = blockIdx.x;
    int tid = threadIdx.x;
    const float* xr = X + (long)row * D;
    float v0 = xr[tid], v1 = xr[tid + 256], v2 = xr[tid + 512];
    __shared__ float red[256];
    red[tid] = v0 + v1 + v2;
    __syncthreads();
    for (int o = 128; o > 0; o >>= 1) { if (tid < o) red[tid] += red[tid + o]; __syncthreads(); }
    float mean = red[0] * (1.0f / D);
    __syncthreads();
    float d0 = v0 - mean, d1 = v1 - mean, d2 = v2 - mean;
    red[tid] = d0*d0 + d1*d1 + d2*d2;
    __syncthreads();
    for (int o = 128; o > 0; o >>= 1) { if (tid < o) red[tid] += red[tid + o]; __syncthreads(); }
    float rs = rsqrtf(red[0] * (1.0f / D) + 1e-5f);
    float* yr = Y + (long)row * D;
    yr[tid]       = d0 * rs * g[tid]       + be[tid];
    yr[tid + 256] = d1 * rs * g[tid + 256] + be[tid + 256];
    yr[tid + 512] = d2 * rs * g[tid + 512] + be[tid + 512];
}

// ---------------- softmax over m, then gate by sigmoid(lm) ----------------
__global__ void softmax_gate(float* __restrict__ attn, const float* __restrict__ lm) {
    int n = blockIdx.x, h = blockIdx.y, bt = blockIdx.z;
    long base = (((long)(bt * NHD + h)) * NT + n) * NT;
    int tid = threadIdx.x;
    float v = (tid < NT) ? attn[base + tid] : -1e30f;
    __shared__ float red[256];
    red[tid] = v;
    __syncthreads();
    for (int o = 128; o > 0; o >>= 1) { if (tid < o) red[tid] = fmaxf(red[tid], red[tid + o]); __syncthreads(); }
    float mx = red[0];
    __syncthreads();
    float e = (tid < NT) ? expf(v - mx) : 0.f;
    red[tid] = e;
    __syncthreads();
    for (int o = 128; o > 0; o >>= 1) { if (tid < o) red[tid] += red[tid + o]; __syncthreads(); }
    float inv = 1.0f / red[0];
    if (tid < NT) {
        float gate = lm[((long)(bt * NT + n)) * NT + tid];
        attn[base + tid] = e * inv * gate;
    }
}

// ---------------- o = attn @ v  (per bt,head; NN gemm, K=197) ----------------
__global__ __launch_bounds__(256) void av_kernel(
    const float* __restrict__ attn, const float* __restrict__ qkv, float* __restrict__ o)
{
    int n0 = blockIdx.x * 32;
    int h  = blockIdx.y;
    int bt = blockIdx.z;
    const float* Ab = attn + ((long)(bt * NHD + h)) * NT * NT;
    const float* Vb = qkv + (long)bt * NT * 3 * D + 2 * D + h * HD;

    __shared__ float Asm[32][33];
    __shared__ __align__(16) float Vsm[32][64];
    int tid = threadIdx.x;
    int tx = tid & 15, ty = tid >> 4;
    float acc[2][4] = {{0.f,0.f,0.f,0.f},{0.f,0.f,0.f,0.f}};

    int r  = tid >> 3;            // 0..31
    int c0 = (tid & 7) * 4;       // attn cols
    int c2 = (tid & 7) * 8;       // v cols

    for (int m0 = 0; m0 < NT; m0 += 32) {
        __syncthreads();
        #pragma unroll
        for (int j = 0; j < 4; j++) {
            int n = n0 + r, m = m0 + c0 + j;
            Asm[r][c0 + j] = (n < NT && m < NT) ? Ab[(long)n * NT + m] : 0.f;
        }
        if (m0 + r < NT) {
            const float* vp = Vb + (long)(m0 + r) * (3 * D) + c2;
            float4 u0 = *(const float4*)vp;
            float4 u1 = *(const float4*)(vp + 4);
            Vsm[r][c2+0]=u0.x; Vsm[r][c2+1]=u0.y; Vsm[r][c2+2]=u0.z; Vsm[r][c2+3]=u0.w;
            Vsm[r][c2+4]=u1.x; Vsm[r][c2+5]=u1.y; Vsm[r][c2+6]=u1.z; Vsm[r][c2+7]=u1.w;
        } else {
            #pragma unroll
            for (int j = 0; j < 8; j++) Vsm[r][c2 + j] = 0.f;
        }
        __syncthreads();
        #pragma unroll
        for (int k = 0; k < 32; k++) {
            float a0 = Asm[ty*2][k], a1 = Asm[ty*2+1][k];
            float4 b4 = *(const float4*)&Vsm[k][tx*4];
            acc[0][0] = fmaf(a0, b4.x, acc[0][0]); acc[0][1] = fmaf(a0, b4.y, acc[0][1]);
            acc[0][2] = fmaf(a0, b4.z, acc[0][2]); acc[0][3] = fmaf(a0, b4.w, acc[0][3]);
            acc[1][0] = fmaf(a1, b4.x, acc[1][0]); acc[1][1] = fmaf(a1, b4.y, acc[1][1]);
            acc[1][2] = fmaf(a1, b4.z, acc[1][2]); acc[1][3] = fmaf(a1, b4.w, acc[1][3]);
        }
    }
    #pragma unroll
    for (int i = 0; i < 2; i++) {
        int n = n0 + ty*2 + i;
        if (n >= NT) continue;
        #pragma unroll
        for (int j = 0; j < 4; j++)
            o[((long)(bt * NT + n)) * D + h * HD + tx*4 + j] = acc[i][j];
    }
}

// ---------------- scatter back + residual: y = x + concat(mean cls, spatial) ----------------
__global__ void scatter_y(const float* __restrict__ x, const float* __restrict__ op,
                          float* __restrict__ y, int total) {
    int idx = blockIdx.x * blockDim.x + threadIdx.x;
    if (idx >= total) return;
    int d   = idx % D;
    int row = idx / D;
    int p = row % ST;
    int b = row / ST;
    float add;
    if (p == 0) {
        float s = 0.f;
        #pragma unroll
        for (int t = 0; t < TT; t++)
            s += op[((long)((b * TT + t) * NT)) * D + d];
        add = s * (1.0f / TT);
    } else {
        int q = p - 1;
        int hw = q / TT, t = q % TT;
        add = op[((long)((b * TT + t) * NT + 1 + hw)) * D + d];
    }
    y[idx] = x[idx] + add;
}

// ---------------- launcher ----------------
extern "C" void kernel_launch(void* const* d_in, const int* in_sizes, int n_in,
                              void* d_out, int out_size) {
    const float* x    = (const float*)d_in[0];
    const float* Wmq  = (const float*)d_in[1];
    const float* bmq  = (const float*)d_in[2];
    const float* Wmk  = (const float*)d_in[3];
    const float* bmk  = (const float*)d_in[4];
    const float* g1   = (const float*)d_in[5];
    const float* be1  = (const float*)d_in[6];
    const float* Wqkv = (const float*)d_in[7];
    const float* Wpr  = (const float*)d_in[8];
    const float* bpr  = (const float*)d_in[9];
    const float* g2   = (const float*)d_in[10];
    const float* be2  = (const float*)d_in[11];
    const float* Wf1  = (const float*)d_in[12];
    const float* bf1  = (const float*)d_in[13];
    const float* Wf2  = (const float*)d_in[14];
    const float* bf2  = (const float*)d_in[15];

    float* out = (float*)d_out;
    float* y   = out;
    float* lm  = out + YSZ;

    float *xt, *qm, *km, *xn, *qkv, *attn, *o, *op, *h;
    cudaGetSymbolAddress((void**)&xt,  g_xt);
    cudaGetSymbolAddress((void**)&qm,  g_qm);
    cudaGetSymbolAddress((void**)&km,  g_km);
    cudaGetSymbolAddress((void**)&xn,  g_xn);
    cudaGetSymbolAddress((void**)&qkv, g_qkv);
    cudaGetSymbolAddress((void**)&attn,g_attn);
    cudaGetSymbolAddress((void**)&o,   g_o);
    cudaGetSymbolAddress((void**)&op,  g_op);
    cudaGetSymbolAddress((void**)&h,   g_h);

    // 1) gather to frame-token layout
    gather_xt<<<(MXT * D + 255) / 256, 256>>>(x, xt, MXT * D);

    // 2) mask projections qm, km
    sgemm_nt<<<dim3(D/128, (MXT+127)/128), 256>>>(xt, Wmq, bmq, nullptr, qm, MXT, D, D, 0);
    sgemm_nt<<<dim3(D/128, (MXT+127)/128), 256>>>(xt, Wmk, bmk, nullptr, km, MXT, D, D, 0);

    // 3) lm logits (batched NT over bt), then sigmoid with forced [0,0]=100
    bgemm_nt<<<dim3(4, 4, BT), 256>>>(qm, km, lm, NT, NT, D, D, D, NT,
                                      1, 0, 0, (long long)NT * D, (long long)NT * D,
                                      (long long)NT * NT, 1.0f);
    sigmoid_lm<<<(LMSZ + 255) / 256, 256>>>(lm, LMSZ);

    // 4) LN1, QKV projection (no bias)
    ln_kernel<<<MXT, 256>>>(xt, g1, be1, xn);
    sgemm_nt<<<dim3((3*D)/128, (MXT+127)/128), 256>>>(xn, Wqkv, nullptr, nullptr, qkv, MXT, 3*D, D, 0);

    // 5) attention scores (batched over bt*heads), softmax + gate, AV
    bgemm_nt<<<dim3(4, 4, BT * NHD), 256>>>(qkv, qkv + D, attn, NT, NT, HD, 3*D, 3*D, NT,
                                            NHD, HD, HD,
                                            (long long)NT * 3 * D, (long long)NT * 3 * D,
                                            (long long)NT * NT, 0.125f);
    softmax_gate<<<dim3(NT, NHD, BT), 256>>>(attn, lm);
    av_kernel<<<dim3(7, NHD, BT), 256>>>(attn, qkv, o);

    // 6) output projection, scatter back (+residual)
    sgemm_nt<<<dim3(D/128, (MXT+127)/128), 256>>>(o, Wpr, bpr, nullptr, op, MXT, D, D, 0);
    scatter_y<<<(YSZ + 255) / 256, 256>>>(x, op, y, YSZ);

    // 7) MLP: LN2 -> fc1(+gelu) -> fc2(+residual into y)
    ln_kernel<<<MY, 256>>>(y, g2, be2, xn);   // reuse xn buffer (rows 12552 <= 12608)
    sgemm_nt<<<dim3(DH/128, (MY+127)/128), 256>>>(xn, Wf1, bf1, nullptr, h, MY, DH, D, 1);
    sgemm_nt<<<dim3(D/128, (MY+127)/128), 256>>>(h, Wf2, bf2, y, y, MY, D, DH, 2);
}

// round 2
// speedup vs baseline: 3.3604x; 3.3604x over previous
#include <cuda_runtime.h>
#include <math.h>

// ---------------- problem constants ----------------
#define D    768
#define DH   3072
#define BB   8
#define TT   8
#define NT   197            // tokens per frame (cls + 196)
#define BT   64             // B*T
#define NHD  12             // heads
#define HD   64             // head dim
#define ST   1569           // T*H*W + 1
#define MXT  (BT*NT)        // 12608 rows in frame-token space
#define MY   (BB*ST)        // 12552 rows in original token space
#define YSZ  (MY*D)         // 9,639,936
#define LMSZ (BT*NT*NT)     // 2,483,776

// ---------------- scratch (device globals: allocation-free) ----------------
__device__ float g_xt [MXT*D];
__device__ float g_qm [MXT*D];
__device__ float g_km [MXT*D];
__device__ float g_xn [MXT*D];        // reused: LN1 out, later LN2 out
__device__ float g_qkv[MXT*3*D];
__device__ float g_attn[(long)BT*NHD*NT*NT];
__device__ float g_o  [MXT*D];
__device__ float g_op [MXT*D];
__device__ float g_h  [MY*DH];

// ---------------- helpers ----------------
__device__ __forceinline__ float tf32r(float x) {
    unsigned r;
    asm("cvt.rna.tf32.f32 %0, %1;" : "=r"(r) : "f"(x));
    return __uint_as_float(r);
}

__device__ __forceinline__ void mma8(float* c, const unsigned* a, const unsigned* b) {
    asm volatile(
        "mma.sync.aligned.m16n8k8.row.col.f32.tf32.tf32.f32 "
        "{%0,%1,%2,%3}, {%4,%5,%6,%7}, {%8,%9}, {%0,%1,%2,%3};"
        : "+f"(c[0]), "+f"(c[1]), "+f"(c[2]), "+f"(c[3])
        : "r"(a[0]), "r"(a[1]), "r"(a[2]), "r"(a[3]), "r"(b[0]), "r"(b[1]));
}

// ---------------- gather x -> xt (frame-token layout) ----------------
__global__ void gather_xt(const float* __restrict__ x, float* __restrict__ xt, int total) {
    int idx = blockIdx.x * blockDim.x + threadIdx.x;
    if (idx >= total) return;
    int d   = idx % D;
    int row = idx / D;
    int n   = row % NT;
    int bt  = row / NT;
    int b = bt / TT, t = bt % TT;
    int src = (n == 0) ? (b * ST) : (b * ST + 1 + (n - 1) * TT + t);
    xt[idx] = x[(long)src * D + d];
}

// ---------------- universal tf32 tensor-core GEMM: C = epi(alpha*A*B^T + bias) ----------------
// A: M x K (lda), B: N x K (ldb), both row-major. Optional batching via blockIdx.z
// (enabled when sC != 0): zo = z/inner, zi = z%inner.
// ep: 0 = (+bias), 1 = (+bias, gelu), 2 = (+bias, +Res)
__global__ __launch_bounds__(256, 2) void gemm_tf32(
    const float* __restrict__ A, const float* __restrict__ B,
    const float* __restrict__ bias, const float* __restrict__ Res,
    float* __restrict__ C, int M, int N, int K,
    int lda, int ldb, int ldc,
    int inner, int sAi, int sBi, long long sAo, long long sBo, long long sC,
    float alpha, int ep)
{
    __shared__ float As[128][20];   // [m][k], stride 20 -> conflict-free frag loads
    __shared__ float Bs[128][20];   // [n][k]

    int tid  = threadIdx.x;
    int warp = tid >> 5, lane = tid & 31;
    int g = lane >> 2, tig = lane & 3;
    int wm = warp >> 2;     // 0..1 : 64 rows each
    int wn = warp & 3;      // 0..3 : 32 cols each
    int m0 = blockIdx.y * 128, n0 = blockIdx.x * 128;

    const float* Ab = A;
    const float* Bb = B;
    float* Cb = C;
    if (sC) {
        int z = blockIdx.z;
        int zo = z / inner, zi = z % inner;
        Ab += (long long)zo * sAo + (long long)zi * sAi;
        Bb += (long long)zo * sBo + (long long)zi * sBi;
        Cb += (long long)z * sC;
    }

    int ldrow = tid >> 1;          // 0..127
    int ldcol = (tid & 1) * 8;     // 0 or 8
    bool aok = (m0 + ldrow) < M;
    bool bok = (n0 + ldrow) < N;
    const float* Ap = Ab + (long long)(m0 + ldrow) * lda + ldcol;
    const float* Bp = Bb + (long long)(n0 + ldrow) * ldb + ldcol;

    const float4 f4z = make_float4(0.f, 0.f, 0.f, 0.f);
    float4 ar0 = aok ? *(const float4*)(Ap)     : f4z;
    float4 ar1 = aok ? *(const float4*)(Ap + 4) : f4z;
    float4 br0 = bok ? *(const float4*)(Bp)     : f4z;
    float4 br1 = bok ? *(const float4*)(Bp + 4) : f4z;

    float acc[4][4][4];
    #pragma unroll
    for (int mt = 0; mt < 4; mt++)
        #pragma unroll
        for (int nt = 0; nt < 4; nt++)
            #pragma unroll
            for (int i = 0; i < 4; i++) acc[mt][nt][i] = 0.f;

    int nkt = K >> 4;
    for (int kt = 0; kt < nkt; kt++) {
        // store staged tile (convert to tf32 at STS)
        {
            float4 t;
            t = ar0; t.x = tf32r(t.x); t.y = tf32r(t.y); t.z = tf32r(t.z); t.w = tf32r(t.w);
            *(float4*)&As[ldrow][ldcol] = t;
            t = ar1; t.x = tf32r(t.x); t.y = tf32r(t.y); t.z = tf32r(t.z); t.w = tf32r(t.w);
            *(float4*)&As[ldrow][ldcol + 4] = t;
            t = br0; t.x = tf32r(t.x); t.y = tf32r(t.y); t.z = tf32r(t.z); t.w = tf32r(t.w);
            *(float4*)&Bs[ldrow][ldcol] = t;
            t = br1; t.x = tf32r(t.x); t.y = tf32r(t.y); t.z = tf32r(t.z); t.w = tf32r(t.w);
            *(float4*)&Bs[ldrow][ldcol + 4] = t;
        }
        __syncthreads();

        // prefetch next k-tile into registers
        if (kt + 1 < nkt) {
            const float* An = Ap + (kt + 1) * 16;
            const float* Bn = Bp + (kt + 1) * 16;
            ar0 = aok ? *(const float4*)(An)     : f4z;
            ar1 = aok ? *(const float4*)(An + 4) : f4z;
            br0 = bok ? *(const float4*)(Bn)     : f4z;
            br1 = bok ? *(const float4*)(Bn + 4) : f4z;
        }

        #pragma unroll
        for (int ks = 0; ks < 2; ks++) {
            int kk = ks * 8;
            unsigned a[4][4], b[4][2];
            #pragma unroll
            for (int mt = 0; mt < 4; mt++) {
                int r = wm * 64 + mt * 16 + g;
                a[mt][0] = __float_as_uint(As[r][kk + tig]);
                a[mt][1] = __float_as_uint(As[r + 8][kk + tig]);
                a[mt][2] = __float_as_uint(As[r][kk + tig + 4]);
                a[mt][3] = __float_as_uint(As[r + 8][kk + tig + 4]);
            }
            #pragma unroll
            for (int nt = 0; nt < 4; nt++) {
                int r = wn * 32 + nt * 8 + g;
                b[nt][0] = __float_as_uint(Bs[r][kk + tig]);
                b[nt][1] = __float_as_uint(Bs[r][kk + tig + 4]);
            }
            #pragma unroll
            for (int mt = 0; mt < 4; mt++)
                #pragma unroll
                for (int nt = 0; nt < 4; nt++)
                    mma8(acc[mt][nt], a[mt], b[nt]);
        }
        __syncthreads();
    }

    // epilogue
    #pragma unroll
    for (int mt = 0; mt < 4; mt++) {
        int r0 = m0 + wm * 64 + mt * 16 + g;
        #pragma unroll
        for (int nt = 0; nt < 4; nt++) {
            int c0 = n0 + wn * 32 + nt * 8 + tig * 2;
            #pragma unroll
            for (int i = 0; i < 2; i++) {
                int rr = r0 + i * 8;
                if (rr >= M) continue;
                #pragma unroll
                for (int j = 0; j < 2; j++) {
                    int cc = c0 + j;
                    if (cc >= N) continue;
                    float v = acc[mt][nt][i * 2 + j] * alpha;
                    if (bias) v += bias[cc];
                    if (ep == 1) v = 0.5f * v * (1.0f + erff(v * 0.7071067811865476f));
                    else if (ep == 2) v += Res[(long long)rr * ldc + cc];
                    Cb[(long long)rr * ldc + cc] = v;
                }
            }
        }
    }
}

// ---------------- sigmoid over lm logits (with forced [0,0]=100) ----------------
__global__ void sigmoid_lm(float* __restrict__ lm, int total) {
    int idx = blockIdx.x * blockDim.x + threadIdx.x;
    if (idx >= total) return;
    int r = idx % (NT * NT);
    float v = (r == 0) ? 100.0f : lm[idx];
    lm[idx] = 1.0f / (1.0f + expf(-v));
}

// ---------------- LayerNorm over rows of 768 ----------------
__global__ void ln_kernel(const float* __restrict__ X, const float* __restrict__ g,
                          const float* __restrict__ be, float* __restrict__ Y) {
    int row = blockIdx.x;
    int tid = threadIdx.x;
    const float* xr = X + (long)row * D;
    float v0 = xr[tid], v1 = xr[tid + 256], v2 = xr[tid + 512];
    __shared__ float red[256];
    red[tid] = v0 + v1 + v2;
    __syncthreads();
    for (int o = 128; o > 0; o >>= 1) { if (tid < o) red[tid] += red[tid + o]; __syncthreads(); }
    float mean = red[0] * (1.0f / D);
    __syncthreads();
    float d0 = v0 - mean, d1 = v1 - mean, d2 = v2 - mean;
    red[tid] = d0*d0 + d1*d1 + d2*d2;
    __syncthreads();
    for (int o = 128; o > 0; o >>= 1) { if (tid < o) red[tid] += red[tid + o]; __syncthreads(); }
    float rs = rsqrtf(red[0] * (1.0f / D) + 1e-5f);
    float* yr = Y + (long)row * D;
    yr[tid]       = d0 * rs * g[tid]       + be[tid];
    yr[tid + 256] = d1 * rs * g[tid + 256] + be[tid + 256];
    yr[tid + 512] = d2 * rs * g[tid + 512] + be[tid + 512];
}

// ---------------- softmax over m, then gate by sigmoid(lm) ----------------
__global__ void softmax_gate(float* __restrict__ attn, const float* __restrict__ lm) {
    int n = blockIdx.x, h = blockIdx.y, bt = blockIdx.z;
    long base = (((long)(bt * NHD + h)) * NT + n) * NT;
    int tid = threadIdx.x;
    float v = (tid < NT) ? attn[base + tid] : -1e30f;
    __shared__ float red[256];
    red[tid] = v;
    __syncthreads();
    for (int o = 128; o > 0; o >>= 1) { if (tid < o) red[tid] = fmaxf(red[tid], red[tid + o]); __syncthreads(); }
    float mx = red[0];
    __syncthreads();
    float e = (tid < NT) ? expf(v - mx) : 0.f;
    red[tid] = e;
    __syncthreads();
    for (int o = 128; o > 0; o >>= 1) { if (tid < o) red[tid] += red[tid + o]; __syncthreads(); }
    float inv = 1.0f / red[0];
    if (tid < NT) {
        float gate = lm[((long)(bt * NT + n)) * NT + tid];
        attn[base + tid] = e * inv * gate;
    }
}

// ---------------- o = attn @ v  (per bt,head; NN gemm, K=197) ----------------
__global__ __launch_bounds__(256) void av_kernel(
    const float* __restrict__ attn, const float* __restrict__ qkv, float* __restrict__ o)
{
    int n0 = blockIdx.x * 32;
    int h  = blockIdx.y;
    int bt = blockIdx.z;
    const float* Ab = attn + ((long)(bt * NHD + h)) * NT * NT;
    const float* Vb = qkv + (long)bt * NT * 3 * D + 2 * D + h * HD;

    __shared__ float Asm[32][33];
    __shared__ __align__(16) float Vsm[32][64];
    int tid = threadIdx.x;
    int tx = tid & 15, ty = tid >> 4;
    float acc[2][4] = {{0.f,0.f,0.f,0.f},{0.f,0.f,0.f,0.f}};

    int r  = tid >> 3;            // 0..31
    int c0 = (tid & 7) * 4;       // attn cols
    int c2 = (tid & 7) * 8;       // v cols

    for (int m0 = 0; m0 < NT; m0 += 32) {
        __syncthreads();
        #pragma unroll
        for (int j = 0; j < 4; j++) {
            int n = n0 + r, m = m0 + c0 + j;
            Asm[r][c0 + j] = (n < NT && m < NT) ? Ab[(long)n * NT + m] : 0.f;
        }
        if (m0 + r < NT) {
            const float* vp = Vb + (long)(m0 + r) * (3 * D) + c2;
            float4 u0 = *(const float4*)vp;
            float4 u1 = *(const float4*)(vp + 4);
            Vsm[r][c2+0]=u0.x; Vsm[r][c2+1]=u0.y; Vsm[r][c2+2]=u0.z; Vsm[r][c2+3]=u0.w;
            Vsm[r][c2+4]=u1.x; Vsm[r][c2+5]=u1.y; Vsm[r][c2+6]=u1.z; Vsm[r][c2+7]=u1.w;
        } else {
            #pragma unroll
            for (int j = 0; j < 8; j++) Vsm[r][c2 + j] = 0.f;
        }
        __syncthreads();
        #pragma unroll
        for (int k = 0; k < 32; k++) {
            float a0 = Asm[ty*2][k], a1 = Asm[ty*2+1][k];
            float4 b4 = *(const float4*)&Vsm[k][tx*4];
            acc[0][0] = fmaf(a0, b4.x, acc[0][0]); acc[0][1] = fmaf(a0, b4.y, acc[0][1]);
            acc[0][2] = fmaf(a0, b4.z, acc[0][2]); acc[0][3] = fmaf(a0, b4.w, acc[0][3]);
            acc[1][0] = fmaf(a1, b4.x, acc[1][0]); acc[1][1] = fmaf(a1, b4.y, acc[1][1]);
            acc[1][2] = fmaf(a1, b4.z, acc[1][2]); acc[1][3] = fmaf(a1, b4.w, acc[1][3]);
        }
    }
    #pragma unroll
    for (int i = 0; i < 2; i++) {
        int n = n0 + ty*2 + i;
        if (n >= NT) continue;
        #pragma unroll
        for (int j = 0; j < 4; j++)
            o[((long)(bt * NT + n)) * D + h * HD + tx*4 + j] = acc[i][j];
    }
}

// ---------------- scatter back + residual: y = x + concat(mean cls, spatial) ----------------
__global__ void scatter_y(const float* __restrict__ x, const float* __restrict__ op,
                          float* __restrict__ y, int total) {
    int idx = blockIdx.x * blockDim.x + threadIdx.x;
    if (idx >= total) return;
    int d   = idx % D;
    int row = idx / D;
    int p = row % ST;
    int b = row / ST;
    float add;
    if (p == 0) {
        float s = 0.f;
        #pragma unroll
        for (int t = 0; t < TT; t++)
            s += op[((long)((b * TT + t) * NT)) * D + d];
        add = s * (1.0f / TT);
    } else {
        int q = p - 1;
        int hw = q / TT, t = q % TT;
        add = op[((long)((b * TT + t) * NT + 1 + hw)) * D + d];
    }
    y[idx] = x[idx] + add;
}

// ---------------- launcher ----------------
extern "C" void kernel_launch(void* const* d_in, const int* in_sizes, int n_in,
                              void* d_out, int out_size) {
    const float* x    = (const float*)d_in[0];
    const float* Wmq  = (const float*)d_in[1];
    const float* bmq  = (const float*)d_in[2];
    const float* Wmk  = (const float*)d_in[3];
    const float* bmk  = (const float*)d_in[4];
    const float* g1   = (const float*)d_in[5];
    const float* be1  = (const float*)d_in[6];
    const float* Wqkv = (const float*)d_in[7];
    const float* Wpr  = (const float*)d_in[8];
    const float* bpr  = (const float*)d_in[9];
    const float* g2   = (const float*)d_in[10];
    const float* be2  = (const float*)d_in[11];
    const float* Wf1  = (const float*)d_in[12];
    const float* bf1  = (const float*)d_in[13];
    const float* Wf2  = (const float*)d_in[14];
    const float* bf2  = (const float*)d_in[15];

    float* out = (float*)d_out;
    float* y   = out;
    float* lm  = out + YSZ;

    float *xt, *qm, *km, *xn, *qkv, *attn, *o, *op, *h;
    cudaGetSymbolAddress((void**)&xt,  g_xt);
    cudaGetSymbolAddress((void**)&qm,  g_qm);
    cudaGetSymbolAddress((void**)&km,  g_km);
    cudaGetSymbolAddress((void**)&xn,  g_xn);
    cudaGetSymbolAddress((void**)&qkv, g_qkv);
    cudaGetSymbolAddress((void**)&attn,g_attn);
    cudaGetSymbolAddress((void**)&o,   g_o);
    cudaGetSymbolAddress((void**)&op,  g_op);
    cudaGetSymbolAddress((void**)&h,   g_h);

    int gy  = (MXT + 127) / 128;   // 99
    int gy2 = (MY  + 127) / 128;   // 99

    // 1) gather to frame-token layout
    gather_xt<<<(MXT * D + 255) / 256, 256>>>(x, xt, MXT * D);

    // 2) mask projections qm, km (tf32)
    gemm_tf32<<<dim3(D/128, gy), 256>>>(xt, Wmq, bmq, nullptr, qm, MXT, D, D,
                                        D, D, D, 1,0,0,0,0,0, 1.0f, 0);
    gemm_tf32<<<dim3(D/128, gy), 256>>>(xt, Wmk, bmk, nullptr, km, MXT, D, D,
                                        D, D, D, 1,0,0,0,0,0, 1.0f, 0);

    // 3) lm logits (batched over bt), sigmoid with forced [0,0]=100
    gemm_tf32<<<dim3(2, 2, BT), 256>>>(qm, km, nullptr, nullptr, lm, NT, NT, D,
                                       D, D, NT,
                                       1, 0, 0, (long long)NT*D, (long long)NT*D,
                                       (long long)NT*NT, 1.0f, 0);
    sigmoid_lm<<<(LMSZ + 255) / 256, 256>>>(lm, LMSZ);

    // 4) LN1, QKV projection (no bias)
    ln_kernel<<<MXT, 256>>>(xt, g1, be1, xn);
    gemm_tf32<<<dim3((3*D)/128, gy), 256>>>(xn, Wqkv, nullptr, nullptr, qkv, MXT, 3*D, D,
                                            D, D, 3*D, 1,0,0,0,0,0, 1.0f, 0);

    // 5) attention scores (batched over bt*heads, tf32), softmax + gate, AV
    gemm_tf32<<<dim3(2, 2, BT * NHD), 256>>>(qkv, qkv + D, nullptr, nullptr, attn, NT, NT, HD,
                                             3*D, 3*D, NT,
                                             NHD, HD, HD,
                                             (long long)NT*3*D, (long long)NT*3*D,
                                             (long long)NT*NT, 0.125f, 0);
    softmax_gate<<<dim3(NT, NHD, BT), 256>>>(attn, lm);
    av_kernel<<<dim3(7, NHD, BT), 256>>>(attn, qkv, o);

    // 6) output projection, scatter back (+residual)
    gemm_tf32<<<dim3(D/128, gy), 256>>>(o, Wpr, bpr, nullptr, op, MXT, D, D,
                                        D, D, D, 1,0,0,0,0,0, 1.0f, 0);
    scatter_y<<<(YSZ + 255) / 256, 256>>>(x, op, y, YSZ);

    // 7) MLP: LN2 -> fc1(+gelu) -> fc2(+residual into y)
    ln_kernel<<<MY, 256>>>(y, g2, be2, xn);   // reuse xn buffer (rows 12552 <= 12608)
    gemm_tf32<<<dim3(DH/128, gy2), 256>>>(xn, Wf1, bf1, nullptr, h, MY, DH, D,
                                          D, D, DH, 1,0,0,0,0,0, 1.0f, 1);
    gemm_tf32<<<dim3(D/128, gy2), 256>>>(h, Wf2, bf2, y, y, MY, D, DH,
                                         DH, DH, D, 1,0,0,0,0,0, 1.0f, 2);
}